// round 6
// baseline (speedup 1.0000x reference)
#include <cuda_runtime.h>
#include <cstdint>

#define T_SEQ 4096
#define E_DIM 256
#define O_DIM 50257
#define NCHUNK 128           // 128 chunks of 32 timesteps
#define CH 32
#define GT 64                // gemm t-tile
#define GO 128               // gemm o-tile (per warp: 4 o's x 32 lanes)
#define N_OT ((O_DIM + GO - 1) / GO)   // 393
#define N_TT (T_SEQ / GT)              // 64
#define NBLK 148
#define NTHR 512
#define RSTRIDE 36           // padded row stride (floats): 16B aligned, bank-spread

// ---------------- device globals (no allocation allowed) --------------------
__device__ float g_xg[T_SEQ * 40];        // [t][d], d = gate*10+unit; i/f/o pre-scaled 0.5
__device__ float g_h2[T_SEQ * 10];        // h2 = 2*h
__device__ volatile int g_flag[NCHUNK];   // embed chunk ready flags
__device__ volatile int g_prog;           // recurrence progress (timesteps done)
__device__ int g_ticket;                  // gemm work ticket

// ---------------- helpers ---------------------------------------------------
__device__ __forceinline__ float fast_tanh(float x) {
    float y;
    asm("tanh.approx.f32 %0, %1;" : "=f"(y) : "f"(x));
    return y;
}

// ---------------- init kernel -----------------------------------------------
__global__ void init_kernel() {
    int i = threadIdx.x;
    if (i < NCHUNK) g_flag[i] = 0;
    if (i == 0) { g_prog = 0; g_ticket = 0; }
}

// ---------------- recurrence block (block NBLK-1) ---------------------------
// warp 0: serial LSTM; warp 1: gmem->smem staging WITH per-lane transpose.

struct RecShared {
    float xa[2][32 * RSTRIDE];    // [buf][lane][t] : dot dA = lane
    float xb[2][32 * RSTRIDE];    // [buf][lane][t] : dot dB = 30 + lane%10
    volatile int ready[2];
};

__device__ void staging_warp(RecShared* sh) {
    const int lane = threadIdx.x & 31;
    for (int ck = 0; ck < NCHUNK; ck++) {
        const int b = ck & 1;
        while (sh->ready[b] != 0) __nanosleep(64);       // wait buffer free
        while (g_flag[ck] == 0) __nanosleep(64);         // wait producer
        __threadfence();                                  // acquire
        const float* src = &g_xg[ck * CH * 40];
        float* xa = sh->xa[b];
        float* xb = sh->xb[b];
#pragma unroll
        for (int q = 0; q < (CH * 40) / 32; q++) {
            const int idx = q * 32 + lane;
            const int t = idx / 40;
            const int d = idx % 40;
            const float v = __ldg(src + idx);
            if (d < 32) xa[d * RSTRIDE + t] = v;
            if (d >= 30) {
                const int u = d - 30;
                xb[u * RSTRIDE + t] = v;
                xb[(u + 10) * RSTRIDE + t] = v;
                xb[(u + 20) * RSTRIDE + t] = v;
                if (u < 2) xb[(u + 30) * RSTRIDE + t] = v;
            }
        }
        __syncwarp();
        __threadfence_block();
        if (lane == 0) sh->ready[b] = 1;
    }
}

// 10-dot with 4-way split accumulators: depth = 3 FMA + add tree
__device__ __forceinline__ float dot10(const float* w, const float* hk, float x0) {
    float a = fmaf(w[0], hk[0], x0);
    a = fmaf(w[1], hk[1], a);
    a = fmaf(w[2], hk[2], a);
    float b = w[3] * hk[3];
    b = fmaf(w[4], hk[4], b);
    b = fmaf(w[5], hk[5], b);
    float d = w[6] * hk[6];
    d = fmaf(w[7], hk[7], d);
    d = fmaf(w[8], hk[8], d);
    float e = w[9] * hk[9];
    return (a + b) + (d + e);
}

__device__ void recurrence_warp(const float* __restrict__ w_hh, RecShared* sh) {
    const int lane = threadIdx.x;
    const int j = lane % 10;          // unit owned (replicated across lane groups)
    const int dA = lane;              // dots 0..31: i(0-9), f(10-19), g(20-29), o units 0,1
    const int dB = 30 + j;            // o-dot of unit j -> 'to' is LOCAL

    float wA[10], wB[10];
    const float sA = ((dA / 10) == 2) ? 0.5f : 0.25f;
#pragma unroll
    for (int k = 0; k < 10; k++) {
        wA[k] = w_hh[dA * 10 + k] * sA;
        wB[k] = w_hh[dB * 10 + k] * 0.25f;
    }

    float hk[10];
#pragma unroll
    for (int k = 0; k < 10; k++) hk[k] = 0.f;
    float c = 0.f;

    for (int ck = 0; ck < NCHUNK; ck++) {
        const int b = ck & 1;
        while (sh->ready[b] == 0) __nanosleep(32);
        __threadfence_block();
        const float* xaP = sh->xa[b] + lane * RSTRIDE;
        const float* xbP = sh->xb[b] + lane * RSTRIDE;
        const int t0 = ck * CH;

        float4 xa4 = *(const float4*)xaP;
        float4 xb4 = *(const float4*)xbP;

#pragma unroll
        for (int gg = 0; gg < 8; gg++) {
            float4 xa_n, xb_n;
            if (gg < 7) {
                xa_n = *(const float4*)(xaP + (gg + 1) * 4);
                xb_n = *(const float4*)(xbP + (gg + 1) * 4);
            }
            const float xav[4] = {xa4.x, xa4.y, xa4.z, xa4.w};
            const float xbv[4] = {xb4.x, xb4.y, xb4.z, xb4.w};
#pragma unroll
            for (int s = 0; s < 4; s++) {
                const int t = t0 + gg * 4 + s;

                const float tA = fast_tanh(dot10(wA, hk, xav[s]));
                const float tB = fast_tanh(dot10(wB, hk, xbv[s]));

                // gather i/f/g for unit j; o is local (tB)
                const float ti = __shfl_sync(0xffffffffu, tA, j);
                const float tf = __shfl_sync(0xffffffffu, tA, 10 + j);
                const float tg = __shfl_sync(0xffffffffu, tA, 20 + j);
                const float to = tB;

                // c = 0.5*(tf*c + c) + 0.5*(ti*tg + tg) ; h2 = (to+1)*tanh(c)
                const float bbv = fmaf(ti, tg, tg);
                const float hb  = 0.5f * bbv;
                const float aa  = fmaf(tf, c, c);
                c = fmaf(0.5f, aa, hb);
                const float tc = fast_tanh(c);
                const float h2v = fmaf(to, tc, tc);

                if (lane < 10) g_h2[t * 10 + lane] = h2v;

                // broadcast h2 (lanes 0-9 own units 0-9)
#pragma unroll
                for (int k = 0; k < 10; k++)
                    hk[k] = __shfl_sync(0xffffffffu, h2v, k);
            }
            xa4 = xa_n;
            xb4 = xb_n;
        }

        // free buffer + publish progress (release)
        __syncwarp();
        if (lane == 0) sh->ready[b] = 0;
        __threadfence();
        if (lane == 0) g_prog = t0 + CH;
    }
}

// ---------------- gemm consumer (all other warps) ---------------------------
__device__ void gemm_consumer(const float* __restrict__ W_out,
                              const float* __restrict__ b_out,
                              float* __restrict__ out) {
    const int lane = threadIdx.x & 31;
    const int total = N_TT * N_OT;

    for (;;) {
        int tk;
        if (lane == 0) tk = atomicAdd(&g_ticket, 1);
        tk = __shfl_sync(0xffffffffu, tk, 0);
        if (tk >= total) return;

        const int tt = tk / N_OT;
        const int ot = tk - tt * N_OT;
        const int t0 = tt * GT;
        const int o0 = ot * GO + lane;

        float w[4][10], bb[4];
        bool val[4];
#pragma unroll
        for (int r = 0; r < 4; r++) {
            int o = o0 + 32 * r;
            val[r] = (o < O_DIM);
            bb[r] = val[r] ? __ldg(b_out + o) : 0.f;
#pragma unroll
            for (int k = 0; k < 10; k++)
                w[r][k] = val[r] ? 0.5f * __ldg(W_out + (size_t)o * 10 + k) : 0.f;
        }

        const int need = t0 + GT;
        while (g_prog < need) __nanosleep(256);
        __threadfence();

        float hcur = (lane < 10) ? __ldg(&g_h2[t0 * 10 + lane]) : 0.f;
        for (int t = t0; t < t0 + GT; t++) {
            int tn = t + 1; if (tn > T_SEQ - 1) tn = T_SEQ - 1;
            float hnext = (lane < 10) ? __ldg(&g_h2[tn * 10 + lane]) : 0.f;
            float hk[10];
#pragma unroll
            for (int k = 0; k < 10; k++)
                hk[k] = __shfl_sync(0xffffffffu, hcur, k);
            const size_t rb = (size_t)t * O_DIM;
#pragma unroll
            for (int r = 0; r < 4; r++) {
                if (val[r]) {
                    float acc = bb[r];
#pragma unroll
                    for (int k = 0; k < 10; k++) acc = fmaf(w[r][k], hk[k], acc);
                    out[rb + o0 + 32 * r] = acc;
                }
            }
            hcur = hnext;
        }
    }
}

// ---------------- fused persistent kernel -----------------------------------
__global__ void __launch_bounds__(NTHR, 1)
fused_kernel(const int* __restrict__ x,
             const float* __restrict__ emb,
             const float* __restrict__ w_ih,
             const float* __restrict__ b_ih,
             const float* __restrict__ b_hh,
             const float* __restrict__ w_hh,
             const float* __restrict__ W_out,
             const float* __restrict__ b_out,
             float* __restrict__ out) {
    const int b = blockIdx.x;
    const int tid = threadIdx.x;

    // --- dedicated recurrence block ---
    if (b == NBLK - 1) {
        __shared__ RecShared sh;
        if (tid == 0) { sh.ready[0] = 0; sh.ready[1] = 0; }
        __syncthreads();
        if (tid < 32) recurrence_warp(w_hh, &sh);
        else if (tid < 64) staging_warp(&sh);
        return;
    }

    // --- embed phase: block b < 128 computes xg for t in [32b, 32b+32) ---
    if (b < NCHUNK) {
        for (int i = tid; i < CH * 40; i += NTHR) {
            const int t = b * CH + i / 40;
            const int r = i % 40;
            const float4* e = (const float4*)(emb + (size_t)__ldg(x + t) * E_DIM);
            const float4* wv4 = (const float4*)(w_ih + (size_t)r * E_DIM);
            float a0 = 0.f, a1 = 0.f, a2 = 0.f, a3 = 0.f;
#pragma unroll 8
            for (int q = 0; q < E_DIM / 4; q++) {
                float4 ev = __ldg(e + q);
                float4 wv = __ldg(wv4 + q);
                a0 += ev.x * wv.x;
                a1 += ev.y * wv.y;
                a2 += ev.z * wv.z;
                a3 += ev.w * wv.w;
            }
            float v = (__ldg(b_ih + r) + __ldg(b_hh + r)) + ((a0 + a1) + (a2 + a3));
            if (r / 10 != 2) v *= 0.5f;        // sigmoid half-angle fold
            g_xg[t * 40 + r] = v;
        }
        __syncthreads();
        __threadfence();
        if (tid == 0) g_flag[b] = 1;
    }

    // --- gemm phase: everyone drains tickets ---
    gemm_consumer(W_out, b_out, out);
}

// ---------------- launch ----------------------------------------------------
extern "C" void kernel_launch(void* const* d_in, const int* in_sizes, int n_in,
                              void* d_out, int out_size) {
    const int*   x     = (const int*)d_in[0];
    const float* emb   = (const float*)d_in[1];
    const float* w_ih  = (const float*)d_in[2];
    const float* w_hh  = (const float*)d_in[3];
    const float* b_ih  = (const float*)d_in[4];
    const float* b_hh  = (const float*)d_in[5];
    const float* W_out = (const float*)d_in[6];
    const float* b_out = (const float*)d_in[7];
    float* out = (float*)d_out;

    init_kernel<<<1, 256>>>();
    fused_kernel<<<NBLK, NTHR>>>(x, emb, w_ih, b_ih, b_hh, w_hh, W_out, b_out, out);
}

// round 7
// speedup vs baseline: 1.0247x; 1.0247x over previous
#include <cuda_runtime.h>
#include <cstdint>

#define T_SEQ 4096
#define E_DIM 256
#define O_DIM 50257
#define NCHUNK 128           // 128 chunks of 32 timesteps
#define CH 32
#define GT 64                // gemm t-tile
#define GO 128               // gemm o-tile (per warp: 4 o's x 32 lanes)
#define N_OT ((O_DIM + GO - 1) / GO)   // 393
#define N_TT (T_SEQ / GT)              // 64
#define NBLK 148
#define NTHR 512
#define RSTRIDE 36           // padded row stride (floats): 16B aligned, bank-spread

// ---------------- device globals (no allocation allowed) --------------------
__device__ float g_xg[T_SEQ * 40];        // [t][d], d = gate*10+unit; i/f/o pre-scaled 0.5
__device__ float g_h2[T_SEQ * 10];        // h2 = 2*h
__device__ volatile int g_flag[NCHUNK];   // embed chunk ready flags
__device__ volatile int g_prog;           // recurrence progress (timesteps done)
__device__ int g_ticket;                  // gemm work ticket

// ---------------- helpers ---------------------------------------------------
__device__ __forceinline__ float fast_tanh(float x) {
    float y;
    asm("tanh.approx.f32 %0, %1;" : "=f"(y) : "f"(x));
    return y;
}

// ---------------- init kernel -----------------------------------------------
__global__ void init_kernel() {
    int i = threadIdx.x;
    if (i < NCHUNK) g_flag[i] = 0;
    if (i == 0) { g_prog = 0; g_ticket = 0; }
}

// ---------------- recurrence block (block NBLK-1) ---------------------------
// warp 0: serial LSTM; warp 1: gmem->smem staging WITH per-lane transpose.

struct RecShared {
    float xa[2][32 * RSTRIDE];    // [buf][lane][t] : dot dA = lane
    float xb[2][32 * RSTRIDE];    // [buf][lane][t] : dot dB = 30 + lane%10
    volatile int ready[2];
};

__device__ void staging_warp(RecShared* sh) {
    const int lane = threadIdx.x & 31;
    for (int ck = 0; ck < NCHUNK; ck++) {
        const int b = ck & 1;
        while (sh->ready[b] != 0) __nanosleep(64);       // wait buffer free
        while (g_flag[ck] == 0) __nanosleep(64);         // wait producer
        __threadfence();                                  // acquire
        const float* src = &g_xg[ck * CH * 40];
        float* xa = sh->xa[b];
        float* xb = sh->xb[b];
#pragma unroll
        for (int q = 0; q < (CH * 40) / 32; q++) {
            const int idx = q * 32 + lane;
            const int t = idx / 40;
            const int d = idx % 40;
            const float v = __ldg(src + idx);
            if (d < 32) xa[d * RSTRIDE + t] = v;
            if (d >= 30) {
                const int u = d - 30;
                xb[u * RSTRIDE + t] = v;
                xb[(u + 10) * RSTRIDE + t] = v;
                xb[(u + 20) * RSTRIDE + t] = v;
                if (u < 2) xb[(u + 30) * RSTRIDE + t] = v;
            }
        }
        __syncwarp();
        __threadfence_block();
        if (lane == 0) sh->ready[b] = 1;
    }
}

// 10-dot with 4-way split accumulators: depth = 3 FMA + add tree
__device__ __forceinline__ float dot10(const float* w, const float* hk, float x0) {
    float a = fmaf(w[0], hk[0], x0);
    a = fmaf(w[1], hk[1], a);
    a = fmaf(w[2], hk[2], a);
    float b = w[3] * hk[3];
    b = fmaf(w[4], hk[4], b);
    b = fmaf(w[5], hk[5], b);
    float d = w[6] * hk[6];
    d = fmaf(w[7], hk[7], d);
    d = fmaf(w[8], hk[8], d);
    float e = w[9] * hk[9];
    return (a + b) + (d + e);
}

__device__ void recurrence_warp(const float* __restrict__ w_hh, RecShared* sh) {
    const int lane = threadIdx.x;
    const int j = lane % 10;          // unit owned (replicated across lane groups)
    const int dA = lane;              // dots 0..31: i(0-9), f(10-19), g(20-29), o units 0,1
    const int dB = 30 + j;            // o-dot of unit j -> 'to' is LOCAL

    float wA[10], wB[10];
    const float sA = ((dA / 10) == 2) ? 0.5f : 0.25f;
#pragma unroll
    for (int k = 0; k < 10; k++) {
        wA[k] = w_hh[dA * 10 + k] * sA;
        wB[k] = w_hh[dB * 10 + k] * 0.25f;
    }

    float hk[10];
#pragma unroll
    for (int k = 0; k < 10; k++) hk[k] = 0.f;
    float c = 0.f;

    for (int ck = 0; ck < NCHUNK; ck++) {
        const int b = ck & 1;
        while (sh->ready[b] == 0) __nanosleep(32);
        __threadfence_block();
        const float* xaP = sh->xa[b] + lane * RSTRIDE;
        const float* xbP = sh->xb[b] + lane * RSTRIDE;
        const int t0 = ck * CH;

        float4 xa4 = *(const float4*)xaP;
        float4 xb4 = *(const float4*)xbP;

#pragma unroll
        for (int gg = 0; gg < 8; gg++) {
            float4 xa_n, xb_n;
            if (gg < 7) {
                xa_n = *(const float4*)(xaP + (gg + 1) * 4);
                xb_n = *(const float4*)(xbP + (gg + 1) * 4);
            }
            const float xav[4] = {xa4.x, xa4.y, xa4.z, xa4.w};
            const float xbv[4] = {xb4.x, xb4.y, xb4.z, xb4.w};
#pragma unroll
            for (int s = 0; s < 4; s++) {
                const int t = t0 + gg * 4 + s;

                const float tA = fast_tanh(dot10(wA, hk, xav[s]));
                const float tB = fast_tanh(dot10(wB, hk, xbv[s]));

                // gather i/f/g for unit j; o is local (tB)
                const float ti = __shfl_sync(0xffffffffu, tA, j);
                const float tf = __shfl_sync(0xffffffffu, tA, 10 + j);
                const float tg = __shfl_sync(0xffffffffu, tA, 20 + j);
                const float to = tB;

                // c = 0.5*(tf*c + c) + 0.5*(ti*tg + tg) ; h2 = (to+1)*tanh(c)
                const float bbv = fmaf(ti, tg, tg);
                const float hb  = 0.5f * bbv;
                const float aa  = fmaf(tf, c, c);
                c = fmaf(0.5f, aa, hb);
                const float tc = fast_tanh(c);
                const float h2v = fmaf(to, tc, tc);

                if (lane < 10) g_h2[t * 10 + lane] = h2v;

                // broadcast h2 (lanes 0-9 own units 0-9)
#pragma unroll
                for (int k = 0; k < 10; k++)
                    hk[k] = __shfl_sync(0xffffffffu, h2v, k);
            }
            xa4 = xa_n;
            xb4 = xb_n;
        }

        // free buffer + publish progress (release)
        __syncwarp();
        if (lane == 0) sh->ready[b] = 0;
        __threadfence();
        if (lane == 0) g_prog = t0 + CH;
    }
}

// ---------------- gemm consumer (all other warps) ---------------------------
__device__ void gemm_consumer(const float* __restrict__ W_out,
                              const float* __restrict__ b_out,
                              float* __restrict__ out) {
    const int lane = threadIdx.x & 31;
    const int total = N_TT * N_OT;

    for (;;) {
        int tk;
        if (lane == 0) tk = atomicAdd(&g_ticket, 1);
        tk = __shfl_sync(0xffffffffu, tk, 0);
        if (tk >= total) return;

        const int tt = tk / N_OT;
        const int ot = tk - tt * N_OT;
        const int t0 = tt * GT;
        const int o0 = ot * GO + lane;

        float w[4][10], bb[4];
        bool val[4];
#pragma unroll
        for (int r = 0; r < 4; r++) {
            int o = o0 + 32 * r;
            val[r] = (o < O_DIM);
            bb[r] = val[r] ? __ldg(b_out + o) : 0.f;
#pragma unroll
            for (int k = 0; k < 10; k++)
                w[r][k] = val[r] ? 0.5f * __ldg(W_out + (size_t)o * 10 + k) : 0.f;
        }

        const int need = t0 + GT;
        while (g_prog < need) __nanosleep(256);
        __threadfence();

        float hcur = (lane < 10) ? __ldg(&g_h2[t0 * 10 + lane]) : 0.f;
        for (int t = t0; t < t0 + GT; t++) {
            int tn = t + 1; if (tn > T_SEQ - 1) tn = T_SEQ - 1;
            float hnext = (lane < 10) ? __ldg(&g_h2[tn * 10 + lane]) : 0.f;
            float hk[10];
#pragma unroll
            for (int k = 0; k < 10; k++)
                hk[k] = __shfl_sync(0xffffffffu, hcur, k);
            const size_t rb = (size_t)t * O_DIM;
#pragma unroll
            for (int r = 0; r < 4; r++) {
                if (val[r]) {
                    float acc = bb[r];
#pragma unroll
                    for (int k = 0; k < 10; k++) acc = fmaf(w[r][k], hk[k], acc);
                    out[rb + o0 + 32 * r] = acc;
                }
            }
            hcur = hnext;
        }
    }
}

// ---------------- fused persistent kernel -----------------------------------
__global__ void __launch_bounds__(NTHR, 1)
fused_kernel(const int* __restrict__ x,
             const float* __restrict__ emb,
             const float* __restrict__ w_ih,
             const float* __restrict__ b_ih,
             const float* __restrict__ b_hh,
             const float* __restrict__ w_hh,
             const float* __restrict__ W_out,
             const float* __restrict__ b_out,
             float* __restrict__ out) {
    const int b = blockIdx.x;
    const int tid = threadIdx.x;

    // --- dedicated recurrence block ---
    if (b == NBLK - 1) {
        __shared__ RecShared sh;
        if (tid == 0) { sh.ready[0] = 0; sh.ready[1] = 0; }
        __syncthreads();
        if (tid < 32) recurrence_warp(w_hh, &sh);
        else if (tid < 64) staging_warp(&sh);
        return;
    }

    // --- embed phase: block b < 128 computes xg for t in [32b, 32b+32) ---
    if (b < NCHUNK) {
        for (int i = tid; i < CH * 40; i += NTHR) {
            const int t = b * CH + i / 40;
            const int r = i % 40;
            const float4* e = (const float4*)(emb + (size_t)__ldg(x + t) * E_DIM);
            const float4* wv4 = (const float4*)(w_ih + (size_t)r * E_DIM);
            float a0 = 0.f, a1 = 0.f, a2 = 0.f, a3 = 0.f;
#pragma unroll 8
            for (int q = 0; q < E_DIM / 4; q++) {
                float4 ev = __ldg(e + q);
                float4 wv = __ldg(wv4 + q);
                a0 += ev.x * wv.x;
                a1 += ev.y * wv.y;
                a2 += ev.z * wv.z;
                a3 += ev.w * wv.w;
            }
            float v = (__ldg(b_ih + r) + __ldg(b_hh + r)) + ((a0 + a1) + (a2 + a3));
            if (r / 10 != 2) v *= 0.5f;        // sigmoid half-angle fold
            g_xg[t * 40 + r] = v;
        }
        __syncthreads();
        __threadfence();
        if (tid == 0) g_flag[b] = 1;
    }

    // --- gemm phase: everyone drains tickets ---
    gemm_consumer(W_out, b_out, out);
}

// ---------------- launch ----------------------------------------------------
extern "C" void kernel_launch(void* const* d_in, const int* in_sizes, int n_in,
                              void* d_out, int out_size) {
    const int*   x     = (const int*)d_in[0];
    const float* emb   = (const float*)d_in[1];
    const float* w_ih  = (const float*)d_in[2];
    const float* w_hh  = (const float*)d_in[3];
    const float* b_ih  = (const float*)d_in[4];
    const float* b_hh  = (const float*)d_in[5];
    const float* W_out = (const float*)d_in[6];
    const float* b_out = (const float*)d_in[7];
    float* out = (float*)d_out;

    init_kernel<<<1, 256>>>();
    fused_kernel<<<NBLK, NTHR>>>(x, emb, w_ih, b_ih, b_hh, w_hh, W_out, b_out, out);
}

// round 8
// speedup vs baseline: 6.2115x; 6.0620x over previous
#include <cuda_runtime.h>
#include <cstdint>

#define T_SEQ 4096
#define E_DIM 256
#define O_DIM 50257
#define NCHUNK 128           // 128 chunks of 32 timesteps
#define CH 32
#define GT 64                // gemm t-tile
#define GO 128               // gemm o-tile (per warp: 4 o's x 32 lanes)
#define N_OT ((O_DIM + GO - 1) / GO)   // 393
#define N_TT (T_SEQ / GT)              // 64
#define NBLK 148
#define NTHR 512

// ---------------- device globals (no allocation allowed) --------------------
__device__ float g_xg[T_SEQ * 40];        // [t][d], d = gate*10+unit; i/f/o pre-scaled 0.5
__device__ float g_h2[T_SEQ * 10];        // h2 = 2*h
__device__ volatile int g_flag[NCHUNK];   // embed chunk ready flags
__device__ volatile int g_prog;           // recurrence progress (timesteps done)
__device__ int g_ticket;                  // gemm work ticket

// ---------------- helpers ---------------------------------------------------
__device__ __forceinline__ float fast_tanh(float x) {
    float y;
    asm("tanh.approx.f32 %0, %1;" : "=f"(y) : "f"(x));
    return y;
}

// ---------------- init kernel -----------------------------------------------
__global__ void init_kernel() {
    int i = threadIdx.x;
    if (i < NCHUNK) g_flag[i] = 0;
    if (i == 0) { g_prog = 0; g_ticket = 0; }
}

// ---------------- recurrence block (block NBLK-1) ---------------------------
// warp 0: serial LSTM; warp 1: xg gmem->smem staging + h2 smem->gmem flushing.

struct RecShared {
    float xg[2][CH * 40];         // xg double buffer, 5KB each
    float h2[2][CH * 10];         // h2 double buffer, 1.25KB each
    volatile int ready[2];        // xg buffer filled
    volatile int hready[2];       // h2 buffer filled (awaiting flush)
};

// flush one finished chunk's h2 from smem to gmem, publish progress
__device__ __forceinline__ void flush_h(RecShared* sh, int ckh, int lane) {
    const int hb = ckh & 1;
    while (sh->hready[hb] == 0) __nanosleep(64);
    __threadfence_block();
    const float* hsrc = sh->h2[hb];
    float* hdst = &g_h2[ckh * CH * 10];
#pragma unroll
    for (int i = 0; i < 10; i++)
        hdst[lane + 32 * i] = hsrc[lane + 32 * i];
    __syncwarp();
    if (lane == 0) sh->hready[hb] = 0;
    __threadfence();                      // h2 stores visible before progress
    if (lane == 0) g_prog = (ckh + 1) * CH;
}

__device__ void staging_warp(RecShared* sh) {
    const int lane = threadIdx.x & 31;
    for (int ck = 0; ck < NCHUNK; ck++) {
        const int b = ck & 1;
        while (sh->ready[b] != 0) __nanosleep(64);       // wait xg buffer free
        while (g_flag[ck] == 0) __nanosleep(64);         // wait embed producer
        __threadfence();                                  // acquire
        const float4* src = (const float4*)&g_xg[ck * CH * 40];
        float4* dst = (float4*)sh->xg[b];
#pragma unroll
        for (int i = 0; i < 10; i++)
            dst[lane + 32 * i] = __ldg(src + lane + 32 * i);
        __syncwarp();
        __threadfence_block();
        if (lane == 0) sh->ready[b] = 1;

        // flush previous chunk's h while the recurrence works on this one
        if (ck > 0) flush_h(sh, ck - 1, lane);
    }
    flush_h(sh, NCHUNK - 1, lane);
}

// 10-dot with 4-way split accumulators: depth = 3 FMA + add tree
__device__ __forceinline__ float dot10(const float* w, const float* hk, float x0) {
    float a = fmaf(w[0], hk[0], x0);
    a = fmaf(w[1], hk[1], a);
    a = fmaf(w[2], hk[2], a);
    float b = w[3] * hk[3];
    b = fmaf(w[4], hk[4], b);
    b = fmaf(w[5], hk[5], b);
    float d = w[6] * hk[6];
    d = fmaf(w[7], hk[7], d);
    d = fmaf(w[8], hk[8], d);
    float e = w[9] * hk[9];
    return (a + b) + (d + e);
}

__device__ void recurrence_warp(const float* __restrict__ w_hh, RecShared* sh) {
    const int lane = threadIdx.x;
    const int j = lane % 10;          // unit owned (replicated across lane groups)
    const int dA = lane;              // dots 0..31: i(0-9), f(10-19), g(20-29), o units 0,1
    const int dB = 30 + j;            // o-dot of unit j -> 'to' is LOCAL

    float wA[10], wB[10];
    const float sA = ((dA / 10) == 2) ? 0.5f : 0.25f;
#pragma unroll
    for (int k = 0; k < 10; k++) {
        wA[k] = w_hh[dA * 10 + k] * sA;
        wB[k] = w_hh[dB * 10 + k] * 0.25f;
    }

    float hk[10];
#pragma unroll
    for (int k = 0; k < 10; k++) hk[k] = 0.f;
    float c = 0.f;

    for (int ck = 0; ck < NCHUNK; ck++) {
        const int b = ck & 1;
        while (sh->ready[b] == 0) __nanosleep(32);
        __threadfence_block();
        const float* src = sh->xg[b];
        float* hbuf = sh->h2[b];

        float xa = src[dA];
        float xb = src[dB];

#pragma unroll
        for (int tt = 0; tt < CH; tt++) {
            // prefetch next step's xg (clamped inside chunk; compile-time offsets)
            const int tp = (tt < CH - 1) ? tt + 1 : tt;
            const float xa_n = src[tp * 40 + dA];
            const float xb_n = src[tp * 40 + dB];

            const float tA = fast_tanh(dot10(wA, hk, xa));
            const float tB = fast_tanh(dot10(wB, hk, xb));

            // gather i/f/g for unit j; o is local (tB)
            const float ti = __shfl_sync(0xffffffffu, tA, j);
            const float tf = __shfl_sync(0xffffffffu, tA, 10 + j);
            const float tg = __shfl_sync(0xffffffffu, tA, 20 + j);
            const float to = tB;

            // c = 0.5*(tf*c + c) + 0.5*(ti*tg + tg) ; h2 = (to+1)*tanh(c)
            const float bbv = fmaf(ti, tg, tg);
            const float hb  = 0.5f * bbv;
            const float aa  = fmaf(tf, c, c);
            c = fmaf(0.5f, aa, hb);
            const float tc = fast_tanh(c);
            const float h2v = fmaf(to, tc, tc);

            // h2 to smem ring (staging warp flushes to gmem)
            if (lane < 10) hbuf[tt * 10 + lane] = h2v;

            // broadcast h2 (lanes 0-9 own units 0-9)
#pragma unroll
            for (int k = 0; k < 10; k++)
                hk[k] = __shfl_sync(0xffffffffu, h2v, k);

            xa = xa_n;
            xb = xb_n;
        }

        // free xg buffer, hand h2 buffer to staging warp
        __syncwarp();
        __threadfence_block();
        if (lane == 0) { sh->ready[b] = 0; sh->hready[b] = 1; }
    }
}

// ---------------- gemm consumer (all other warps) ---------------------------
__device__ void gemm_consumer(const float* __restrict__ W_out,
                              const float* __restrict__ b_out,
                              float* __restrict__ out) {
    const int lane = threadIdx.x & 31;
    const int total = N_TT * N_OT;

    for (;;) {
        int tk;
        if (lane == 0) tk = atomicAdd(&g_ticket, 1);
        tk = __shfl_sync(0xffffffffu, tk, 0);
        if (tk >= total) return;

        const int tt = tk / N_OT;
        const int ot = tk - tt * N_OT;
        const int t0 = tt * GT;
        const int o0 = ot * GO + lane;

        float w[4][10], bb[4];
        bool val[4];
#pragma unroll
        for (int r = 0; r < 4; r++) {
            int o = o0 + 32 * r;
            val[r] = (o < O_DIM);
            bb[r] = val[r] ? __ldg(b_out + o) : 0.f;
#pragma unroll
            for (int k = 0; k < 10; k++)
                w[r][k] = val[r] ? 0.5f * __ldg(W_out + (size_t)o * 10 + k) : 0.f;
        }

        const int need = t0 + GT;
        while (g_prog < need) __nanosleep(1024);
        __threadfence();

        float hcur = (lane < 10) ? __ldg(&g_h2[t0 * 10 + lane]) : 0.f;
        for (int t = t0; t < t0 + GT; t++) {
            int tn = t + 1; if (tn > T_SEQ - 1) tn = T_SEQ - 1;
            float hnext = (lane < 10) ? __ldg(&g_h2[tn * 10 + lane]) : 0.f;
            float hk[10];
#pragma unroll
            for (int k = 0; k < 10; k++)
                hk[k] = __shfl_sync(0xffffffffu, hcur, k);
            const size_t rb = (size_t)t * O_DIM;
#pragma unroll
            for (int r = 0; r < 4; r++) {
                if (val[r]) {
                    float acc = bb[r];
#pragma unroll
                    for (int k = 0; k < 10; k++) acc = fmaf(w[r][k], hk[k], acc);
                    out[rb + o0 + 32 * r] = acc;
                }
            }
            hcur = hnext;
        }
    }
}

// ---------------- fused persistent kernel -----------------------------------
__global__ void __launch_bounds__(NTHR, 1)
fused_kernel(const int* __restrict__ x,
             const float* __restrict__ emb,
             const float* __restrict__ w_ih,
             const float* __restrict__ b_ih,
             const float* __restrict__ b_hh,
             const float* __restrict__ w_hh,
             const float* __restrict__ W_out,
             const float* __restrict__ b_out,
             float* __restrict__ out) {
    const int b = blockIdx.x;
    const int tid = threadIdx.x;

    // --- dedicated recurrence block ---
    if (b == NBLK - 1) {
        __shared__ RecShared sh;
        if (tid == 0) {
            sh.ready[0] = 0; sh.ready[1] = 0;
            sh.hready[0] = 0; sh.hready[1] = 0;
        }
        __syncthreads();
        if (tid < 32) recurrence_warp(w_hh, &sh);
        else if (tid < 64) staging_warp(&sh);
        return;
    }

    // --- embed phase: block b < 128 computes xg for t in [32b, 32b+32) ---
    if (b < NCHUNK) {
        for (int i = tid; i < CH * 40; i += NTHR) {
            const int t = b * CH + i / 40;
            const int r = i % 40;
            const float4* e = (const float4*)(emb + (size_t)__ldg(x + t) * E_DIM);
            const float4* wv4 = (const float4*)(w_ih + (size_t)r * E_DIM);
            float a0 = 0.f, a1 = 0.f, a2 = 0.f, a3 = 0.f;
#pragma unroll 8
            for (int q = 0; q < E_DIM / 4; q++) {
                float4 ev = __ldg(e + q);
                float4 wv = __ldg(wv4 + q);
                a0 += ev.x * wv.x;
                a1 += ev.y * wv.y;
                a2 += ev.z * wv.z;
                a3 += ev.w * wv.w;
            }
            float v = (__ldg(b_ih + r) + __ldg(b_hh + r)) + ((a0 + a1) + (a2 + a3));
            if (r / 10 != 2) v *= 0.5f;        // sigmoid half-angle fold
            g_xg[t * 40 + r] = v;
        }
        __syncthreads();
        __threadfence();
        if (tid == 0) g_flag[b] = 1;
    }

    // --- gemm phase: everyone drains tickets ---
    gemm_consumer(W_out, b_out, out);
}

// ---------------- launch ----------------------------------------------------
extern "C" void kernel_launch(void* const* d_in, const int* in_sizes, int n_in,
                              void* d_out, int out_size) {
    const int*   x     = (const int*)d_in[0];
    const float* emb   = (const float*)d_in[1];
    const float* w_ih  = (const float*)d_in[2];
    const float* w_hh  = (const float*)d_in[3];
    const float* b_ih  = (const float*)d_in[4];
    const float* b_hh  = (const float*)d_in[5];
    const float* W_out = (const float*)d_in[6];
    const float* b_out = (const float*)d_in[7];
    float* out = (float*)d_out;

    init_kernel<<<1, 256>>>();
    fused_kernel<<<NBLK, NTHR>>>(x, emb, w_ih, b_ih, b_hh, w_hh, W_out, b_out, out);
}

// round 9
// speedup vs baseline: 6.2446x; 1.0053x over previous
#include <cuda_runtime.h>
#include <cstdint>

#define T_SEQ 4096
#define E_DIM 256
#define O_DIM 50257
#define NCHUNK 128           // 128 chunks of 32 timesteps
#define CH 32
#define GT 64                // gemm t-tile
#define GO 128               // gemm o-tile (per warp: 4 o's x 32 lanes)
#define N_OT ((O_DIM + GO - 1) / GO)   // 393
#define N_TT (T_SEQ / GT)              // 64
#define NBLK 148
#define NTHR 512

// ---------------- device globals (no allocation allowed) --------------------
__device__ float g_xg[T_SEQ * 40];        // [t][d], d = gate*10+unit; i/f/o pre-scaled 0.5
__device__ float g_h2[T_SEQ * 10];        // h2 = 2*h
__device__ volatile int g_flag[NCHUNK];   // embed chunk ready flags
__device__ volatile int g_prog;           // recurrence progress (timesteps done)
__device__ int g_ticket;                  // gemm work ticket

// ---------------- helpers ---------------------------------------------------
__device__ __forceinline__ float fast_tanh(float x) {
    float y;
    asm("tanh.approx.f32 %0, %1;" : "=f"(y) : "f"(x));
    return y;
}
#define MUL2(d, a, b)    asm("mul.rn.f32x2 %0, %1, %2;" : "=l"(d) : "l"(a), "l"(b))
#define FMA2(d, a, b, c) asm("fma.rn.f32x2 %0, %1, %2, %3;" : "=l"(d) : "l"(a), "l"(b), "l"(c))
#define PK2(d, lo, hi)   asm("mov.b64 %0, {%1, %2};" : "=l"(d) : "f"(lo), "f"(hi))
#define UPK2(lo, hi, s)  asm("mov.b64 {%0, %1}, %2;" : "=f"(lo), "=f"(hi) : "l"(s))

// ---------------- init kernel -----------------------------------------------
__global__ void init_kernel() {
    int i = threadIdx.x;
    if (i < NCHUNK) g_flag[i] = 0;
    if (i == 0) { g_prog = 0; g_ticket = 0; }
}

// ---------------- recurrence block (block NBLK-1) ---------------------------
// warp 0: serial LSTM; warp 1: xg gmem->smem staging + h2 smem->gmem flushing.

struct RecShared {
    float xg[2][CH * 40];         // xg double buffer, 5KB each
    float h2[2][CH * 10];         // h2 double buffer, 1.25KB each
    volatile int ready[2];        // xg buffer filled
    volatile int hready[2];       // h2 buffer filled (awaiting flush)
};

// flush one finished chunk's h2 from smem to gmem, publish progress
__device__ __forceinline__ void flush_h(RecShared* sh, int ckh, int lane) {
    const int hb = ckh & 1;
    while (sh->hready[hb] == 0) __nanosleep(64);
    __threadfence_block();
    const float* hsrc = sh->h2[hb];
    float* hdst = &g_h2[ckh * CH * 10];
#pragma unroll
    for (int i = 0; i < 10; i++)
        hdst[lane + 32 * i] = hsrc[lane + 32 * i];
    __syncwarp();
    if (lane == 0) sh->hready[hb] = 0;
    __threadfence();                      // h2 stores visible before progress
    if (lane == 0) g_prog = (ckh + 1) * CH;
}

__device__ void staging_warp(RecShared* sh) {
    const int lane = threadIdx.x & 31;
    for (int ck = 0; ck < NCHUNK; ck++) {
        const int b = ck & 1;
        while (sh->ready[b] != 0) __nanosleep(64);       // wait xg buffer free
        while (g_flag[ck] == 0) __nanosleep(64);         // wait embed producer
        __threadfence();                                  // acquire
        const float4* src = (const float4*)&g_xg[ck * CH * 40];
        float4* dst = (float4*)sh->xg[b];
#pragma unroll
        for (int i = 0; i < 10; i++)
            dst[lane + 32 * i] = __ldg(src + lane + 32 * i);
        __syncwarp();
        __threadfence_block();
        if (lane == 0) sh->ready[b] = 1;

        // flush previous chunk's h while the recurrence works on this one
        if (ck > 0) flush_h(sh, ck - 1, lane);
    }
    flush_h(sh, NCHUNK - 1, lane);
}

// packed 10-dot: 1 MUL2 + 4 FMA2 + unpack + (lo+hi)+x
__device__ __forceinline__ float dot10p(const unsigned long long* w2,
                                        const unsigned long long* hp, float x0) {
    unsigned long long acc;
    MUL2(acc, w2[0], hp[0]);
    FMA2(acc, w2[1], hp[1], acc);
    FMA2(acc, w2[2], hp[2], acc);
    FMA2(acc, w2[3], hp[3], acc);
    FMA2(acc, w2[4], hp[4], acc);
    float lo, hi;
    UPK2(lo, hi, acc);
    return (lo + hi) + x0;
}

__device__ void recurrence_warp(const float* __restrict__ w_hh, RecShared* sh) {
    const int lane = threadIdx.x;
    const int j = lane % 10;          // unit owned (replicated across lane groups)
    const int dA = lane;              // dots 0..31: i(0-9), f(10-19), g(20-29), o units 0,1
    const int dB = 30 + j;            // o-dot of unit j -> 'to' is LOCAL

    // pre-packed scaled weights (u64 pairs)
    unsigned long long wA2[5], wB2[5];
    {
        const float sA = ((dA / 10) == 2) ? 0.5f : 0.25f;
#pragma unroll
        for (int p = 0; p < 5; p++) {
            PK2(wA2[p], w_hh[dA * 10 + 2 * p] * sA, w_hh[dA * 10 + 2 * p + 1] * sA);
            PK2(wB2[p], w_hh[dB * 10 + 2 * p] * 0.25f, w_hh[dB * 10 + 2 * p + 1] * 0.25f);
        }
    }

    unsigned long long hp[5];
#pragma unroll
    for (int p = 0; p < 5; p++) hp[p] = 0ull;
    float c = 0.f;

    for (int ck = 0; ck < NCHUNK; ck++) {
        const int b = ck & 1;
        while (sh->ready[b] == 0) __nanosleep(32);
        __threadfence_block();
        const float* src = sh->xg[b];
        float* hbuf = sh->h2[b];

        float xa = src[dA];
        float xb = src[dB];

#pragma unroll
        for (int tt = 0; tt < CH; tt++) {
            // prefetch next step's xg (clamped inside chunk; compile-time offsets)
            const int tp = (tt < CH - 1) ? tt + 1 : tt;
            const float xa_n = src[tp * 40 + dA];
            const float xb_n = src[tp * 40 + dB];

            const float tA = fast_tanh(dot10p(wA2, hp, xa));
            const float tB = fast_tanh(dot10p(wB2, hp, xb));

            // gather i/f/g for unit j; o is local (tB)
            const float ti = __shfl_sync(0xffffffffu, tA, j);
            const float tf = __shfl_sync(0xffffffffu, tA, 10 + j);
            const float tg = __shfl_sync(0xffffffffu, tA, 20 + j);

            // c = 0.5*(tf*c + c) + 0.5*(ti*tg + tg) ; h2 = (to+1)*tanh(c)
            const float bbv = fmaf(ti, tg, tg);
            const float hb  = 0.5f * bbv;
            const float aa  = fmaf(tf, c, c);
            c = fmaf(0.5f, aa, hb);
            const float tc = fast_tanh(c);
            const float h2v = fmaf(tB, tc, tc);

            // h2 to smem ring (staging warp flushes to gmem)
            if (lane < 10) hbuf[tt * 10 + lane] = h2v;

            // broadcast h2 (lanes 0-9 own units 0-9) and pack into pairs
            float hk0 = __shfl_sync(0xffffffffu, h2v, 0);
            float hk1 = __shfl_sync(0xffffffffu, h2v, 1);
            float hk2 = __shfl_sync(0xffffffffu, h2v, 2);
            float hk3 = __shfl_sync(0xffffffffu, h2v, 3);
            float hk4 = __shfl_sync(0xffffffffu, h2v, 4);
            float hk5 = __shfl_sync(0xffffffffu, h2v, 5);
            float hk6 = __shfl_sync(0xffffffffu, h2v, 6);
            float hk7 = __shfl_sync(0xffffffffu, h2v, 7);
            float hk8 = __shfl_sync(0xffffffffu, h2v, 8);
            float hk9 = __shfl_sync(0xffffffffu, h2v, 9);
            PK2(hp[0], hk0, hk1);
            PK2(hp[1], hk2, hk3);
            PK2(hp[2], hk4, hk5);
            PK2(hp[3], hk6, hk7);
            PK2(hp[4], hk8, hk9);

            xa = xa_n;
            xb = xb_n;
        }

        // free xg buffer, hand h2 buffer to staging warp
        __syncwarp();
        __threadfence_block();
        if (lane == 0) { sh->ready[b] = 0; sh->hready[b] = 1; }
    }
}

// ---------------- gemm consumer (all other warps) ---------------------------
__device__ void gemm_consumer(const float* __restrict__ W_out,
                              const float* __restrict__ b_out,
                              float* __restrict__ out) {
    const int lane = threadIdx.x & 31;
    const int total = N_TT * N_OT;

    for (;;) {
        int tk;
        if (lane == 0) tk = atomicAdd(&g_ticket, 1);
        tk = __shfl_sync(0xffffffffu, tk, 0);
        if (tk >= total) return;

        const int tt = tk / N_OT;
        const int ot = tk - tt * N_OT;
        const int t0 = tt * GT;
        const int o0 = ot * GO + lane;

        float w[4][10], bb[4];
        bool val[4];
#pragma unroll
        for (int r = 0; r < 4; r++) {
            int o = o0 + 32 * r;
            val[r] = (o < O_DIM);
            bb[r] = val[r] ? __ldg(b_out + o) : 0.f;
#pragma unroll
            for (int k = 0; k < 10; k++)
                w[r][k] = val[r] ? 0.5f * __ldg(W_out + (size_t)o * 10 + k) : 0.f;
        }

        const int need = t0 + GT;
        while (g_prog < need) __nanosleep(1024);
        __threadfence();

        float hcur = (lane < 10) ? __ldg(&g_h2[t0 * 10 + lane]) : 0.f;
        for (int t = t0; t < t0 + GT; t++) {
            int tn = t + 1; if (tn > T_SEQ - 1) tn = T_SEQ - 1;
            float hnext = (lane < 10) ? __ldg(&g_h2[tn * 10 + lane]) : 0.f;
            float hk[10];
#pragma unroll
            for (int k = 0; k < 10; k++)
                hk[k] = __shfl_sync(0xffffffffu, hcur, k);
            const size_t rb = (size_t)t * O_DIM;
#pragma unroll
            for (int r = 0; r < 4; r++) {
                if (val[r]) {
                    float acc = bb[r];
#pragma unroll
                    for (int k = 0; k < 10; k++) acc = fmaf(w[r][k], hk[k], acc);
                    out[rb + o0 + 32 * r] = acc;
                }
            }
            hcur = hnext;
        }
    }
}

// ---------------- fused persistent kernel -----------------------------------
__global__ void __launch_bounds__(NTHR, 1)
fused_kernel(const int* __restrict__ x,
             const float* __restrict__ emb,
             const float* __restrict__ w_ih,
             const float* __restrict__ b_ih,
             const float* __restrict__ b_hh,
             const float* __restrict__ w_hh,
             const float* __restrict__ W_out,
             const float* __restrict__ b_out,
             float* __restrict__ out) {
    const int b = blockIdx.x;
    const int tid = threadIdx.x;

    // --- dedicated recurrence block ---
    if (b == NBLK - 1) {
        __shared__ RecShared sh;
        if (tid == 0) {
            sh.ready[0] = 0; sh.ready[1] = 0;
            sh.hready[0] = 0; sh.hready[1] = 0;
        }
        __syncthreads();
        if (tid < 32) recurrence_warp(w_hh, &sh);
        else if (tid < 64) staging_warp(&sh);
        return;
    }

    // --- embed phase: block b < 128 computes xg for t in [32b, 32b+32) ---
    if (b < NCHUNK) {
        for (int i = tid; i < CH * 40; i += NTHR) {
            const int t = b * CH + i / 40;
            const int r = i % 40;
            const float4* e = (const float4*)(emb + (size_t)__ldg(x + t) * E_DIM);
            const float4* wv4 = (const float4*)(w_ih + (size_t)r * E_DIM);
            float a0 = 0.f, a1 = 0.f, a2 = 0.f, a3 = 0.f;
#pragma unroll 8
            for (int q = 0; q < E_DIM / 4; q++) {
                float4 ev = __ldg(e + q);
                float4 wv = __ldg(wv4 + q);
                a0 += ev.x * wv.x;
                a1 += ev.y * wv.y;
                a2 += ev.z * wv.z;
                a3 += ev.w * wv.w;
            }
            float v = (__ldg(b_ih + r) + __ldg(b_hh + r)) + ((a0 + a1) + (a2 + a3));
            if (r / 10 != 2) v *= 0.5f;        // sigmoid half-angle fold
            g_xg[t * 40 + r] = v;
        }
        __syncthreads();
        __threadfence();
        if (tid == 0) g_flag[b] = 1;
    }

    // --- gemm phase: everyone drains tickets ---
    gemm_consumer(W_out, b_out, out);
}

// ---------------- launch ----------------------------------------------------
extern "C" void kernel_launch(void* const* d_in, const int* in_sizes, int n_in,
                              void* d_out, int out_size) {
    const int*   x     = (const int*)d_in[0];
    const float* emb   = (const float*)d_in[1];
    const float* w_ih  = (const float*)d_in[2];
    const float* w_hh  = (const float*)d_in[3];
    const float* b_ih  = (const float*)d_in[4];
    const float* b_hh  = (const float*)d_in[5];
    const float* W_out = (const float*)d_in[6];
    const float* b_out = (const float*)d_in[7];
    float* out = (float*)d_out;

    init_kernel<<<1, 256>>>();
    fused_kernel<<<NBLK, NTHR>>>(x, emb, w_ih, b_ih, b_hh, w_hh, W_out, b_out, out);
}

// round 10
// speedup vs baseline: 6.4038x; 1.0255x over previous
#include <cuda_runtime.h>
#include <cstdint>

#define T_SEQ 4096
#define E_DIM 256
#define O_DIM 50257
#define NCHUNK 128           // 128 chunks of 32 timesteps
#define CH 32
#define GT 64                // gemm t-tile
#define GO 128               // gemm o-tile (per warp: 4 o's x 32 lanes)
#define N_OT ((O_DIM + GO - 1) / GO)   // 393
#define N_TT (T_SEQ / GT)              // 64
#define NBLK 148
#define NTHR 512

// ---------------- device globals (no allocation allowed) --------------------
__device__ float g_xg[T_SEQ * 40];        // [t][d], d = gate*10+unit; i/f/o pre-scaled 0.5
__device__ float g_h2[T_SEQ * 10];        // h2 = 2*h
__device__ volatile int g_flag[NCHUNK];   // embed chunk ready flags
__device__ volatile int g_prog;           // recurrence progress (timesteps done)
__device__ int g_ticket;                  // gemm work ticket

// ---------------- helpers ---------------------------------------------------
__device__ __forceinline__ float fast_tanh(float x) {
    float y;
    asm("tanh.approx.f32 %0, %1;" : "=f"(y) : "f"(x));
    return y;
}
#define FMA2(d, a, b, c) asm("fma.rn.f32x2 %0, %1, %2, %3;" : "=l"(d) : "l"(a), "l"(b), "l"(c))
#define PK2(d, lo, hi)   asm("mov.b64 %0, {%1, %2};" : "=l"(d) : "f"(lo), "f"(hi))
#define UPK2(lo, hi, s)  asm("mov.b64 {%0, %1}, %2;" : "=f"(lo), "=f"(hi) : "l"(s))

// ---------------- init kernel -----------------------------------------------
__global__ void init_kernel() {
    int i = threadIdx.x;
    if (i < NCHUNK) g_flag[i] = 0;
    if (i == 0) { g_prog = 0; g_ticket = 0; }
}

// ---------------- recurrence block (block NBLK-1) ---------------------------
// warp 0: serial LSTM; warp 1: xg gmem->smem staging + h2 smem->gmem flushing.

struct RecShared {
    float xg[2][CH * 40];         // xg double buffer, 5KB each
    float h2[2][CH * 10];         // h2 double buffer, 1.25KB each
    volatile int ready[2];        // xg buffer filled
    volatile int hready[2];       // h2 buffer filled (awaiting flush)
};

// flush one finished chunk's h2 from smem to gmem, publish progress
__device__ __forceinline__ void flush_h(RecShared* sh, int ckh, int lane) {
    const int hb = ckh & 1;
    while (sh->hready[hb] == 0) __nanosleep(64);
    __threadfence_block();
    const float* hsrc = sh->h2[hb];
    float* hdst = &g_h2[ckh * CH * 10];
#pragma unroll
    for (int i = 0; i < 10; i++)
        hdst[lane + 32 * i] = hsrc[lane + 32 * i];
    __syncwarp();
    if (lane == 0) sh->hready[hb] = 0;
    __threadfence();                      // h2 stores visible before progress
    if (lane == 0) g_prog = (ckh + 1) * CH;
}

__device__ void staging_warp(RecShared* sh) {
    const int lane = threadIdx.x & 31;
    for (int ck = 0; ck < NCHUNK; ck++) {
        const int b = ck & 1;
        while (sh->ready[b] != 0) __nanosleep(64);       // wait xg buffer free
        while (g_flag[ck] == 0) __nanosleep(64);         // wait embed producer
        __threadfence();                                  // acquire
        const float4* src = (const float4*)&g_xg[ck * CH * 40];
        float4* dst = (float4*)sh->xg[b];
#pragma unroll
        for (int i = 0; i < 10; i++)
            dst[lane + 32 * i] = __ldg(src + lane + 32 * i);
        __syncwarp();
        __threadfence_block();
        if (lane == 0) sh->ready[b] = 1;

        // flush previous chunk's h while the recurrence works on this one
        if (ck > 0) flush_h(sh, ck - 1, lane);
    }
    flush_h(sh, NCHUNK - 1, lane);
}

// packed 10-dot with x folded into the accumulator init:
// acc = fma2(w0, hp0, (x,0)); 4 more FMA2; final lo+hi.
__device__ __forceinline__ float dot10px(const unsigned long long* w2,
                                         const unsigned long long* hp,
                                         unsigned long long xpk) {
    unsigned long long acc;
    FMA2(acc, w2[0], hp[0], xpk);
    FMA2(acc, w2[1], hp[1], acc);
    FMA2(acc, w2[2], hp[2], acc);
    FMA2(acc, w2[3], hp[3], acc);
    FMA2(acc, w2[4], hp[4], acc);
    float lo, hi;
    UPK2(lo, hi, acc);
    return lo + hi;
}

__device__ void recurrence_warp(const float* __restrict__ w_hh, RecShared* sh) {
    const int lane = threadIdx.x;
    const int j = lane % 10;          // unit owned (only lanes 0-9's results are consumed)
    const int dA = lane;              // dots 0..31: i(0-9), f(10-19), g(20-29), o units 0,1
    const int dB = 30 + j;            // o-dot of unit j -> 'to' is LOCAL

    // pre-packed scaled weights (u64 pairs)
    unsigned long long wA2[5], wB2[5];
    {
        const float sA = ((dA / 10) == 2) ? 0.5f : 0.25f;
#pragma unroll
        for (int p = 0; p < 5; p++) {
            PK2(wA2[p], w_hh[dA * 10 + 2 * p] * sA, w_hh[dA * 10 + 2 * p + 1] * sA);
            PK2(wB2[p], w_hh[dB * 10 + 2 * p] * 0.25f, w_hh[dB * 10 + 2 * p + 1] * 0.25f);
        }
    }

    unsigned long long hp[5];
#pragma unroll
    for (int p = 0; p < 5; p++) hp[p] = 0ull;
    float c = 0.f;

    for (int ck = 0; ck < NCHUNK; ck++) {
        const int b = ck & 1;
        while (sh->ready[b] == 0) __nanosleep(32);
        __threadfence_block();
        const float* src = sh->xg[b];
        float* hbuf = sh->h2[b];

        unsigned long long xpa, xpb;
        PK2(xpa, src[dA], 0.f);
        PK2(xpb, src[dB], 0.f);

#pragma unroll
        for (int tt = 0; tt < CH; tt++) {
            // prefetch next step's xg (clamped inside chunk; compile-time offsets)
            const int tp = (tt < CH - 1) ? tt + 1 : tt;
            unsigned long long xpa_n, xpb_n;
            PK2(xpa_n, src[tp * 40 + dA], 0.f);
            PK2(xpb_n, src[tp * 40 + dB], 0.f);

            const float tA = fast_tanh(dot10px(wA2, hp, xpa));
            const float tB = fast_tanh(dot10px(wB2, hp, xpb));

            // lane j<10: ti = tA is LOCAL (dA == i-dot of unit j); gather only f,g.
            // lanes >=10 produce garbage c/h that is never consumed.
            const float ti = tA;
            const float tf = __shfl_sync(0xffffffffu, tA, 10 + j);
            const float tg = __shfl_sync(0xffffffffu, tA, 20 + j);

            // c = 0.5*(tf*c + c) + 0.5*(ti*tg + tg) ; h2 = (to+1)*tanh(c)
            const float bbv = fmaf(ti, tg, tg);
            const float hb  = 0.5f * bbv;
            const float aa  = fmaf(tf, c, c);
            c = fmaf(0.5f, aa, hb);
            const float tc = fast_tanh(c);
            const float h2v = fmaf(tB, tc, tc);

            // h2 to smem ring (staging warp flushes to gmem)
            if (lane < 10) hbuf[tt * 10 + lane] = h2v;

            // broadcast h2 (lanes 0-9 own units 0-9) and pack into pairs
            float hk0 = __shfl_sync(0xffffffffu, h2v, 0);
            float hk1 = __shfl_sync(0xffffffffu, h2v, 1);
            float hk2 = __shfl_sync(0xffffffffu, h2v, 2);
            float hk3 = __shfl_sync(0xffffffffu, h2v, 3);
            float hk4 = __shfl_sync(0xffffffffu, h2v, 4);
            float hk5 = __shfl_sync(0xffffffffu, h2v, 5);
            float hk6 = __shfl_sync(0xffffffffu, h2v, 6);
            float hk7 = __shfl_sync(0xffffffffu, h2v, 7);
            float hk8 = __shfl_sync(0xffffffffu, h2v, 8);
            float hk9 = __shfl_sync(0xffffffffu, h2v, 9);
            PK2(hp[0], hk0, hk1);
            PK2(hp[1], hk2, hk3);
            PK2(hp[2], hk4, hk5);
            PK2(hp[3], hk6, hk7);
            PK2(hp[4], hk8, hk9);

            xpa = xpa_n;
            xpb = xpb_n;
        }

        // free xg buffer, hand h2 buffer to staging warp
        __syncwarp();
        __threadfence_block();
        if (lane == 0) { sh->ready[b] = 0; sh->hready[b] = 1; }
    }
}

// ---------------- gemm consumer (all other warps) ---------------------------
__device__ void gemm_consumer(const float* __restrict__ W_out,
                              const float* __restrict__ b_out,
                              float* __restrict__ out) {
    const int lane = threadIdx.x & 31;
    const int total = N_TT * N_OT;

    for (;;) {
        int tk;
        if (lane == 0) tk = atomicAdd(&g_ticket, 1);
        tk = __shfl_sync(0xffffffffu, tk, 0);
        if (tk >= total) return;

        const int tt = tk / N_OT;
        const int ot = tk - tt * N_OT;
        const int t0 = tt * GT;
        const int o0 = ot * GO + lane;

        float w[4][10], bb[4];
        bool val[4];
#pragma unroll
        for (int r = 0; r < 4; r++) {
            int o = o0 + 32 * r;
            val[r] = (o < O_DIM);
            bb[r] = val[r] ? __ldg(b_out + o) : 0.f;
#pragma unroll
            for (int k = 0; k < 10; k++)
                w[r][k] = val[r] ? 0.5f * __ldg(W_out + (size_t)o * 10 + k) : 0.f;
        }

        const int need = t0 + GT;
        while (g_prog < need) __nanosleep(1024);
        __threadfence();

        float hcur = (lane < 10) ? __ldg(&g_h2[t0 * 10 + lane]) : 0.f;
        for (int t = t0; t < t0 + GT; t++) {
            int tn = t + 1; if (tn > T_SEQ - 1) tn = T_SEQ - 1;
            float hnext = (lane < 10) ? __ldg(&g_h2[tn * 10 + lane]) : 0.f;
            float hk[10];
#pragma unroll
            for (int k = 0; k < 10; k++)
                hk[k] = __shfl_sync(0xffffffffu, hcur, k);
            const size_t rb = (size_t)t * O_DIM;
#pragma unroll
            for (int r = 0; r < 4; r++) {
                if (val[r]) {
                    float acc = bb[r];
#pragma unroll
                    for (int k = 0; k < 10; k++) acc = fmaf(w[r][k], hk[k], acc);
                    out[rb + o0 + 32 * r] = acc;
                }
            }
            hcur = hnext;
        }
    }
}

// ---------------- fused persistent kernel -----------------------------------
__global__ void __launch_bounds__(NTHR, 1)
fused_kernel(const int* __restrict__ x,
             const float* __restrict__ emb,
             const float* __restrict__ w_ih,
             const float* __restrict__ b_ih,
             const float* __restrict__ b_hh,
             const float* __restrict__ w_hh,
             const float* __restrict__ W_out,
             const float* __restrict__ b_out,
             float* __restrict__ out) {
    const int b = blockIdx.x;
    const int tid = threadIdx.x;

    // --- dedicated recurrence block ---
    if (b == NBLK - 1) {
        __shared__ RecShared sh;
        if (tid == 0) {
            sh.ready[0] = 0; sh.ready[1] = 0;
            sh.hready[0] = 0; sh.hready[1] = 0;
        }
        __syncthreads();
        if (tid < 32) recurrence_warp(w_hh, &sh);
        else if (tid < 64) staging_warp(&sh);
        return;
    }

    // --- embed phase: block b < 128 computes xg for t in [32b, 32b+32) ---
    if (b < NCHUNK) {
        for (int i = tid; i < CH * 40; i += NTHR) {
            const int t = b * CH + i / 40;
            const int r = i % 40;
            const float4* e = (const float4*)(emb + (size_t)__ldg(x + t) * E_DIM);
            const float4* wv4 = (const float4*)(w_ih + (size_t)r * E_DIM);
            float a0 = 0.f, a1 = 0.f, a2 = 0.f, a3 = 0.f;
#pragma unroll 8
            for (int q = 0; q < E_DIM / 4; q++) {
                float4 ev = __ldg(e + q);
                float4 wv = __ldg(wv4 + q);
                a0 += ev.x * wv.x;
                a1 += ev.y * wv.y;
                a2 += ev.z * wv.z;
                a3 += ev.w * wv.w;
            }
            float v = (__ldg(b_ih + r) + __ldg(b_hh + r)) + ((a0 + a1) + (a2 + a3));
            if (r / 10 != 2) v *= 0.5f;        // sigmoid half-angle fold
            g_xg[t * 40 + r] = v;
        }
        __syncthreads();
        __threadfence();
        if (tid == 0) g_flag[b] = 1;
    }

    // --- gemm phase: everyone drains tickets ---
    gemm_consumer(W_out, b_out, out);
}

// ---------------- launch ----------------------------------------------------
extern "C" void kernel_launch(void* const* d_in, const int* in_sizes, int n_in,
                              void* d_out, int out_size) {
    const int*   x     = (const int*)d_in[0];
    const float* emb   = (const float*)d_in[1];
    const float* w_ih  = (const float*)d_in[2];
    const float* w_hh  = (const float*)d_in[3];
    const float* b_ih  = (const float*)d_in[4];
    const float* b_hh  = (const float*)d_in[5];
    const float* W_out = (const float*)d_in[6];
    const float* b_out = (const float*)d_in[7];
    float* out = (float*)d_out;

    init_kernel<<<1, 256>>>();
    fused_kernel<<<NBLK, NTHR>>>(x, emb, w_ih, b_ih, b_hh, w_hh, W_out, b_out, out);
}

// round 11
// speedup vs baseline: 6.5188x; 1.0180x over previous
#include <cuda_runtime.h>
#include <cstdint>

#define T_SEQ 4096
#define E_DIM 256
#define O_DIM 50257
#define NCHUNK 128           // 128 chunks of 32 timesteps
#define CH 32
#define GT 64                // gemm t-tile
#define GO 128               // gemm o-tile (per warp: 4 o's x 32 lanes)
#define N_OT ((O_DIM + GO - 1) / GO)   // 393
#define N_TT (T_SEQ / GT)              // 64
#define NBLK 148
#define NTHR 512

// ---------------- device globals (no allocation allowed) --------------------
// xg layout: float4 per (t, unit j): (xi*0.5, xf*0.5, xg, xo*0.5)
__device__ float4 g_xg4[T_SEQ * 10];
__device__ float  g_h2[T_SEQ * 10];       // h2 = 2*h
__device__ volatile int g_flag[NCHUNK];   // embed chunk ready flags
__device__ volatile int g_prog;           // recurrence progress (timesteps done)
__device__ int g_ticket;                  // gemm work ticket

// ---------------- helpers ---------------------------------------------------
__device__ __forceinline__ float fast_tanh(float x) {
    float y;
    asm("tanh.approx.f32 %0, %1;" : "=f"(y) : "f"(x));
    return y;
}
#define FMA2(d, a, b, c) asm("fma.rn.f32x2 %0, %1, %2, %3;" : "=l"(d) : "l"(a), "l"(b), "l"(c))
#define MUL2(d, a, b)    asm("mul.rn.f32x2 %0, %1, %2;" : "=l"(d) : "l"(a), "l"(b))
#define ADD2(d, a, b)    asm("add.rn.f32x2 %0, %1, %2;" : "=l"(d) : "l"(a), "l"(b))
#define PK2(d, lo, hi)   asm("mov.b64 %0, {%1, %2};" : "=l"(d) : "f"(lo), "f"(hi))
#define UPK2(lo, hi, s)  asm("mov.b64 {%0, %1}, %2;" : "=f"(lo), "=f"(hi) : "l"(s))

// ---------------- init kernel -----------------------------------------------
__global__ void init_kernel() {
    int i = threadIdx.x;
    if (i < NCHUNK) g_flag[i] = 0;
    if (i == 0) { g_prog = 0; g_ticket = 0; }
}

// ---------------- recurrence block (block NBLK-1) ---------------------------
// warp 0: serial LSTM; warp 1: xg gmem->smem staging + h2 smem->gmem flushing.

struct RecShared {
    float4 xg[2][CH * 10];        // xg double buffer, 5KB each
    float h2[2][CH * 10];         // h2 double buffer, 1.25KB each
    volatile int ready[2];        // xg buffer filled
    volatile int hready[2];       // h2 buffer filled (awaiting flush)
};

// flush one finished chunk's h2 from smem to gmem, publish progress
__device__ __forceinline__ void flush_h(RecShared* sh, int ckh, int lane) {
    const int hb = ckh & 1;
    while (sh->hready[hb] == 0) __nanosleep(64);
    __threadfence_block();
    const float* hsrc = sh->h2[hb];
    float* hdst = &g_h2[ckh * CH * 10];
#pragma unroll
    for (int i = 0; i < 10; i++)
        hdst[lane + 32 * i] = hsrc[lane + 32 * i];
    __syncwarp();
    if (lane == 0) sh->hready[hb] = 0;
    __threadfence();                      // h2 stores visible before progress
    if (lane == 0) g_prog = (ckh + 1) * CH;
}

__device__ void staging_warp(RecShared* sh) {
    const int lane = threadIdx.x & 31;
    for (int ck = 0; ck < NCHUNK; ck++) {
        const int b = ck & 1;
        while (sh->ready[b] != 0) __nanosleep(64);       // wait xg buffer free
        while (g_flag[ck] == 0) __nanosleep(64);         // wait embed producer
        __threadfence();                                  // acquire
        const float4* src = &g_xg4[ck * CH * 10];
        float4* dst = sh->xg[b];
#pragma unroll
        for (int i = 0; i < 10; i++)
            dst[lane + 32 * i] = __ldg(src + lane + 32 * i);
        __syncwarp();
        __threadfence_block();
        if (lane == 0) sh->ready[b] = 1;

        // flush previous chunk's h while the recurrence works on this one
        if (ck > 0) flush_h(sh, ck - 1, lane);
    }
    flush_h(sh, NCHUNK - 1, lane);
}

__device__ void recurrence_warp(const float* __restrict__ w_hh, RecShared* sh) {
    const int lane = threadIdx.x;
    const int j = lane % 10;      // every lane computes unit j (lanes 10-31 redundant)

    // gate-pair-packed scaled weights:
    // wif[k] = (wi[j][k]*0.25, wf[j][k]*0.25)   (sigmoid half-angle x h2 fold)
    // wgo[k] = (wg[j][k]*0.5,  wo[j][k]*0.25)
    unsigned long long wif[10], wgo[10];
#pragma unroll
    for (int k = 0; k < 10; k++) {
        PK2(wif[k], w_hh[(0 * 10 + j) * 10 + k] * 0.25f,
                    w_hh[(1 * 10 + j) * 10 + k] * 0.25f);
        PK2(wgo[k], w_hh[(2 * 10 + j) * 10 + k] * 0.5f,
                    w_hh[(3 * 10 + j) * 10 + k] * 0.25f);
    }

    unsigned long long hd[10];    // duplicated h2 pairs: (h2[k], h2[k])
#pragma unroll
    for (int k = 0; k < 10; k++) hd[k] = 0ull;
    float c = 0.f;

    for (int ck = 0; ck < NCHUNK; ck++) {
        const int b = ck & 1;
        while (sh->ready[b] == 0) __nanosleep(32);
        __threadfence_block();
        const float4* src = sh->xg[b];
        float* hbuf = sh->h2[b];

        float4 xc = src[j];

#pragma unroll
        for (int tt = 0; tt < CH; tt++) {
            // prefetch next step's xg (clamped inside chunk; compile-time offsets)
            const int tp = (tt < CH - 1) ? tt + 1 : tt;
            const float4 xn = src[tp * 10 + j];

            unsigned long long xif, xgo;
            PK2(xif, xc.x, xc.y);
            PK2(xgo, xc.z, xc.w);

            // packed dual-gate dots, 2-way split accumulators
            unsigned long long a1, a2, b1, b2;
            FMA2(a1, wif[0], hd[0], xif);
            FMA2(a1, wif[1], hd[1], a1);
            FMA2(a1, wif[2], hd[2], a1);
            FMA2(a1, wif[3], hd[3], a1);
            FMA2(a1, wif[4], hd[4], a1);
            MUL2(a2, wif[5], hd[5]);
            FMA2(a2, wif[6], hd[6], a2);
            FMA2(a2, wif[7], hd[7], a2);
            FMA2(a2, wif[8], hd[8], a2);
            FMA2(a2, wif[9], hd[9], a2);
            ADD2(a1, a1, a2);

            FMA2(b1, wgo[0], hd[0], xgo);
            FMA2(b1, wgo[1], hd[1], b1);
            FMA2(b1, wgo[2], hd[2], b1);
            FMA2(b1, wgo[3], hd[3], b1);
            FMA2(b1, wgo[4], hd[4], b1);
            MUL2(b2, wgo[5], hd[5]);
            FMA2(b2, wgo[6], hd[6], b2);
            FMA2(b2, wgo[7], hd[7], b2);
            FMA2(b2, wgo[8], hd[8], b2);
            FMA2(b2, wgo[9], hd[9], b2);
            ADD2(b1, b1, b2);

            float pi, pf, pg, po;
            UPK2(pi, pf, a1);
            UPK2(pg, po, b1);

            // all 4 gates LOCAL: no gather shuffles
            const float tg = fast_tanh(pg);
            const float ti = fast_tanh(pi);
            const float tf = fast_tanh(pf);
            const float to = fast_tanh(po);

            // c = 0.5*(tf*c + c) + 0.5*(ti*tg + tg) ; h2 = (to+1)*tanh(c)
            const float bbv = fmaf(ti, tg, tg);
            const float hb  = 0.5f * bbv;
            const float aa  = fmaf(tf, c, c);
            c = fmaf(0.5f, aa, hb);
            const float tc = fast_tanh(c);
            const float h2v = fmaf(to, tc, tc);

            // h2 to smem ring (staging warp flushes to gmem)
            if (lane < 10) hbuf[tt * 10 + lane] = h2v;

            // broadcast h2 (lanes 0-9 own units 0-9), duplicate into pairs
            const float hk0 = __shfl_sync(0xffffffffu, h2v, 0);
            const float hk1 = __shfl_sync(0xffffffffu, h2v, 1);
            const float hk2 = __shfl_sync(0xffffffffu, h2v, 2);
            const float hk3 = __shfl_sync(0xffffffffu, h2v, 3);
            const float hk4 = __shfl_sync(0xffffffffu, h2v, 4);
            const float hk5 = __shfl_sync(0xffffffffu, h2v, 5);
            const float hk6 = __shfl_sync(0xffffffffu, h2v, 6);
            const float hk7 = __shfl_sync(0xffffffffu, h2v, 7);
            const float hk8 = __shfl_sync(0xffffffffu, h2v, 8);
            const float hk9 = __shfl_sync(0xffffffffu, h2v, 9);
            PK2(hd[0], hk0, hk0);
            PK2(hd[1], hk1, hk1);
            PK2(hd[2], hk2, hk2);
            PK2(hd[3], hk3, hk3);
            PK2(hd[4], hk4, hk4);
            PK2(hd[5], hk5, hk5);
            PK2(hd[6], hk6, hk6);
            PK2(hd[7], hk7, hk7);
            PK2(hd[8], hk8, hk8);
            PK2(hd[9], hk9, hk9);

            xc = xn;
        }

        // free xg buffer, hand h2 buffer to staging warp
        __syncwarp();
        __threadfence_block();
        if (lane == 0) { sh->ready[b] = 0; sh->hready[b] = 1; }
    }
}

// ---------------- gemm consumer (all other warps) ---------------------------
__device__ void gemm_consumer(const float* __restrict__ W_out,
                              const float* __restrict__ b_out,
                              float* __restrict__ out) {
    const int lane = threadIdx.x & 31;
    const int total = N_TT * N_OT;

    for (;;) {
        int tk;
        if (lane == 0) tk = atomicAdd(&g_ticket, 1);
        tk = __shfl_sync(0xffffffffu, tk, 0);
        if (tk >= total) return;

        const int tt = tk / N_OT;
        const int ot = tk - tt * N_OT;
        const int t0 = tt * GT;
        const int o0 = ot * GO + lane;

        float w[4][10], bb[4];
        bool val[4];
#pragma unroll
        for (int r = 0; r < 4; r++) {
            int o = o0 + 32 * r;
            val[r] = (o < O_DIM);
            bb[r] = val[r] ? __ldg(b_out + o) : 0.f;
#pragma unroll
            for (int k = 0; k < 10; k++)
                w[r][k] = val[r] ? 0.5f * __ldg(W_out + (size_t)o * 10 + k) : 0.f;
        }

        const int need = t0 + GT;
        while (g_prog < need) __nanosleep(1024);
        __threadfence();

        float hcur = (lane < 10) ? __ldg(&g_h2[t0 * 10 + lane]) : 0.f;
        for (int t = t0; t < t0 + GT; t++) {
            int tn = t + 1; if (tn > T_SEQ - 1) tn = T_SEQ - 1;
            float hnext = (lane < 10) ? __ldg(&g_h2[tn * 10 + lane]) : 0.f;
            float hk[10];
#pragma unroll
            for (int k = 0; k < 10; k++)
                hk[k] = __shfl_sync(0xffffffffu, hcur, k);
            const size_t rb = (size_t)t * O_DIM;
#pragma unroll
            for (int r = 0; r < 4; r++) {
                if (val[r]) {
                    float acc = bb[r];
#pragma unroll
                    for (int k = 0; k < 10; k++) acc = fmaf(w[r][k], hk[k], acc);
                    out[rb + o0 + 32 * r] = acc;
                }
            }
            hcur = hnext;
        }
    }
}

// ---------------- fused persistent kernel -----------------------------------
__global__ void __launch_bounds__(NTHR, 1)
fused_kernel(const int* __restrict__ x,
             const float* __restrict__ emb,
             const float* __restrict__ w_ih,
             const float* __restrict__ b_ih,
             const float* __restrict__ b_hh,
             const float* __restrict__ w_hh,
             const float* __restrict__ W_out,
             const float* __restrict__ b_out,
             float* __restrict__ out) {
    const int b = blockIdx.x;
    const int tid = threadIdx.x;

    // --- dedicated recurrence block ---
    if (b == NBLK - 1) {
        __shared__ RecShared sh;
        if (tid == 0) {
            sh.ready[0] = 0; sh.ready[1] = 0;
            sh.hready[0] = 0; sh.hready[1] = 0;
        }
        __syncthreads();
        if (tid < 32) recurrence_warp(w_hh, &sh);
        else if (tid < 64) staging_warp(&sh);
        return;
    }

    // --- embed phase: block b < 128 computes xg for t in [32b, 32b+32) ---
    if (b < NCHUNK) {
        float* xg = (float*)g_xg4;
        for (int i = tid; i < CH * 40; i += NTHR) {
            const int t = b * CH + i / 40;
            const int r = i % 40;
            const float4* e = (const float4*)(emb + (size_t)__ldg(x + t) * E_DIM);
            const float4* wv4 = (const float4*)(w_ih + (size_t)r * E_DIM);
            float a0 = 0.f, a1 = 0.f, a2 = 0.f, a3 = 0.f;
#pragma unroll 8
            for (int q = 0; q < E_DIM / 4; q++) {
                float4 ev = __ldg(e + q);
                float4 wv = __ldg(wv4 + q);
                a0 += ev.x * wv.x;
                a1 += ev.y * wv.y;
                a2 += ev.z * wv.z;
                a3 += ev.w * wv.w;
            }
            float v = (__ldg(b_ih + r) + __ldg(b_hh + r)) + ((a0 + a1) + (a2 + a3));
            const int gate = r / 10;
            const int u = r - gate * 10;
            if (gate != 2) v *= 0.5f;          // sigmoid half-angle fold (i,f,o)
            xg[(t * 10 + u) * 4 + gate] = v;   // float4 (xi,xf,xg,xo) per (t,unit)
        }
        __syncthreads();
        __threadfence();
        if (tid == 0) g_flag[b] = 1;
    }

    // --- gemm phase: everyone drains tickets ---
    gemm_consumer(W_out, b_out, out);
}

// ---------------- launch ----------------------------------------------------
extern "C" void kernel_launch(void* const* d_in, const int* in_sizes, int n_in,
                              void* d_out, int out_size) {
    const int*   x     = (const int*)d_in[0];
    const float* emb   = (const float*)d_in[1];
    const float* w_ih  = (const float*)d_in[2];
    const float* w_hh  = (const float*)d_in[3];
    const float* b_ih  = (const float*)d_in[4];
    const float* b_hh  = (const float*)d_in[5];
    const float* W_out = (const float*)d_in[6];
    const float* b_out = (const float*)d_in[7];
    float* out = (float*)d_out;

    init_kernel<<<1, 256>>>();
    fused_kernel<<<NBLK, NTHR>>>(x, emb, w_ih, b_ih, b_hh, w_hh, W_out, b_out, out);
}